// round 8
// baseline (speedup 1.0000x reference)
#include <cuda_runtime.h>
#include <cuda_fp16.h>
#include <cstdint>

#define RESULT_ELEMS 16777216   // 64*256*32*32

// smem layout (bytes)
#define OFF_XH    0        // x hi [256][64] half swizzled, 32768
#define OFF_XL    32768    // x lo, 32768
#define OFF_EH    65536    // E chunk hi [128][64] half, 16384
#define OFF_EL    81920    // E chunk lo, 16384
#define OFF_H     98304    // 512 floats
#define OFF_BKS   100352   // 256 ints
#define SMEM_SZ   101376

__device__ float  g_h[512];        // 0.5*||e_k||^2 (exact fp32)
__device__ __half gEh[512 * 64];   // E hi, [n][k]
__device__ __half gEl[512 * 64];   // E lo, [n][k]

__device__ __forceinline__ uint32_t smem_u32(const void* p) {
    uint32_t a;
    asm("{ .reg .u64 t; cvta.to.shared.u64 t, %1; cvt.u32.u64 %0, t; }" : "=r"(a) : "l"(p));
    return a;
}
__device__ __forceinline__ uint32_t sw(uint32_t b) { return b ^ ((b >> 3) & 0x70); }

__device__ __forceinline__ void ldsm4(uint32_t r[4], uint32_t addr) {
    asm volatile("ldmatrix.sync.aligned.m8n8.x4.shared.b16 {%0,%1,%2,%3}, [%4];"
                 : "=r"(r[0]), "=r"(r[1]), "=r"(r[2]), "=r"(r[3]) : "r"(addr));
}
__device__ __forceinline__ void mma16816(float c[4], const uint32_t a[4],
                                         uint32_t b0, uint32_t b1) {
    asm volatile("mma.sync.aligned.m16n8k16.row.col.f32.f16.f16.f32 "
                 "{%0,%1,%2,%3}, {%4,%5,%6,%7}, {%8,%9}, {%0,%1,%2,%3};"
                 : "+f"(c[0]), "+f"(c[1]), "+f"(c[2]), "+f"(c[3])
                 : "r"(a[0]), "r"(a[1]), "r"(a[2]), "r"(a[3]), "r"(b0), "r"(b1));
}

// merged prep: h[k] and E hi/lo split (one launch -> ncu -s 5 lands on vq_mma)
__global__ void prep_kernel(const float* __restrict__ w) {
    int n = threadIdx.x;   // 0..511
    float s = 0.f;
    #pragma unroll
    for (int c = 0; c < 64; ++c) {
        float v = w[c * 512 + n];
        s = fmaf(v, v, s);
        __half h = __float2half_rn(v);
        gEh[n * 64 + c] = h;
        gEl[n * 64 + c] = __float2half_rn(v - __half2float(h));
    }
    g_h[n] = 0.5f * s;
}

__global__ __launch_bounds__(256, 2)
void vq_mma(const float* __restrict__ x, const float* __restrict__ w,
            float* __restrict__ out) {
    extern __shared__ char smem[];
    const uint32_t sb = smem_u32(smem);
    float* hsm = (float*)(smem + OFF_H);
    int*   bks = (int*)(smem + OFF_BKS);

    const int tid = threadIdx.x;
    const int bg  = blockIdx.x >> 2;             // b*4+g
    const int mt  = blockIdx.x & 3;
    const int hw0 = mt * 256;

    // ---- split x tile (256 rows) to fp16 hi/lo directly, swizzled [m][k] ----
    const float* xb = x + (size_t)bg * 65536 + hw0;
    {
        #pragma unroll
        for (int c2 = 0; c2 < 32; ++c2) {
            float v0 = xb[(size_t)(2 * c2) * 1024 + tid];
            float v1 = xb[(size_t)(2 * c2 + 1) * 1024 + tid];
            __half h0 = __float2half_rn(v0), h1 = __float2half_rn(v1);
            __half l0 = __float2half_rn(v0 - __half2float(h0));
            __half l1 = __float2half_rn(v1 - __half2float(h1));
            uint32_t off = sw((uint32_t)(tid * 128 + c2 * 4));
            *(__half2*)(smem + OFF_XH + off) = __halves2half2(h0, h1);
            *(__half2*)(smem + OFF_XL + off) = __halves2half2(l0, l1);
        }
    }
    hsm[tid]       = g_h[tid];
    hsm[tid + 256] = g_h[tid + 256];
    __syncthreads();

    const int w8 = tid >> 5, lane = tid & 31;
    const int m0 = w8 * 32;                      // 32 rows per warp (2 M-tiles)
    const int group = lane >> 2, tig = lane & 3;

    // ---- load all A fragments once: 2 M-tiles x 4 ksteps x (hi,lo) ----
    uint32_t ah[2][4][4], al[2][4][4];
    {
        uint32_t arow = (uint32_t)(lane & 15);
        uint32_t acol = (uint32_t)((lane >> 4) * 16);
        #pragma unroll
        for (int t = 0; t < 2; ++t)
            #pragma unroll
            for (int ks = 0; ks < 4; ++ks) {
                uint32_t off = sw((uint32_t)(m0 + t * 16 + arow) * 128 +
                                  (uint32_t)ks * 32 + acol);
                ldsm4(ah[t][ks], sb + OFF_XH + off);
                ldsm4(al[t][ks], sb + OFF_XL + off);
            }
    }

    float bestv[4];
    int   bestk[4];
    #pragma unroll
    for (int i = 0; i < 4; ++i) { bestv[i] = -3.4e38f; bestk[i] = 0; }

    // B row-addresses (E is [n][k], k contiguous; non-trans ldmatrix)
    const uint32_t brow_l = (uint32_t)((lane & 7) + ((lane >> 4) & 1) * 8);
    const uint32_t bcol_l = (uint32_t)(((lane >> 3) & 1) * 16);

    for (int ch = 0; ch < 4; ++ch) {
        __syncthreads();   // previous chunk's E readers done
        // ---- copy E chunk (128 codes) hi/lo into swizzled smem ----
        #pragma unroll
        for (int i = 0; i < 4; ++i) {
            int u = tid + i * 256;
            int r = u >> 3, seg = u & 7;
            uint32_t off = sw((uint32_t)(r * 128 + seg * 16));
            const char* srch = (const char*)(gEh + (ch * 128 + r) * 64) + seg * 16;
            const char* srcl = (const char*)(gEl + (ch * 128 + r) * 64) + seg * 16;
            *(uint4*)(smem + OFF_EH + off) = *(const uint4*)srch;
            *(uint4*)(smem + OFF_EL + off) = *(const uint4*)srcl;
        }
        __syncthreads();

        for (int jp = 0; jp < 8; ++jp) {       // pairs of 8-code n-tiles
            // split accumulators: 8 independent chains of depth 8
            float cch[2][2][4], ccl[2][2][4];
            #pragma unroll
            for (int t = 0; t < 2; ++t)
                #pragma unroll
                for (int u = 0; u < 2; ++u)
                    #pragma unroll
                    for (int q = 0; q < 4; ++q) { cch[t][u][q] = 0.f; ccl[t][u][q] = 0.f; }

            #pragma unroll
            for (int ks = 0; ks < 4; ++ks) {
                uint32_t boff = sw((uint32_t)(jp * 16 + brow_l) * 128 +
                                   (uint32_t)ks * 32 + bcol_l);
                uint32_t bh[4], bl[4];
                ldsm4(bh, sb + OFF_EH + boff);
                ldsm4(bl, sb + OFF_EL + boff);
                #pragma unroll
                for (int t = 0; t < 2; ++t) {
                    // hi-B terms into cch, lo-B terms into ccl (independent chains)
                    mma16816(cch[t][0], ah[t][ks], bh[0], bh[1]);
                    mma16816(ccl[t][0], ah[t][ks], bl[0], bl[1]);
                    mma16816(cch[t][1], ah[t][ks], bh[2], bh[3]);
                    mma16816(ccl[t][1], ah[t][ks], bl[2], bl[3]);
                    mma16816(cch[t][0], al[t][ks], bh[0], bh[1]);
                    mma16816(ccl[t][0], al[t][ks], bl[0], bl[1]);
                    mma16816(cch[t][1], al[t][ks], bh[2], bh[3]);
                    mma16816(ccl[t][1], al[t][ks], bl[2], bl[3]);
                }
            }
            // ---- fused argmax: ascending n per thread, strict > ----
            int nb = ch * 128 + jp * 16;
            float h0 = hsm[nb + 2 * tig];
            float h1 = hsm[nb + 2 * tig + 1];
            float h2 = hsm[nb + 8 + 2 * tig];
            float h3 = hsm[nb + 8 + 2 * tig + 1];
            #pragma unroll
            for (int t = 0; t < 2; ++t) {
                float s;
                s = (cch[t][0][0] + ccl[t][0][0]) - h0; if (s > bestv[t*2]) { bestv[t*2] = s; bestk[t*2] = nb + 2*tig; }
                s = (cch[t][0][1] + ccl[t][0][1]) - h1; if (s > bestv[t*2]) { bestv[t*2] = s; bestk[t*2] = nb + 2*tig + 1; }
                s = (cch[t][1][0] + ccl[t][1][0]) - h2; if (s > bestv[t*2]) { bestv[t*2] = s; bestk[t*2] = nb + 8 + 2*tig; }
                s = (cch[t][1][1] + ccl[t][1][1]) - h3; if (s > bestv[t*2]) { bestv[t*2] = s; bestk[t*2] = nb + 8 + 2*tig + 1; }
                s = (cch[t][0][2] + ccl[t][0][2]) - h0; if (s > bestv[t*2+1]) { bestv[t*2+1] = s; bestk[t*2+1] = nb + 2*tig; }
                s = (cch[t][0][3] + ccl[t][0][3]) - h1; if (s > bestv[t*2+1]) { bestv[t*2+1] = s; bestk[t*2+1] = nb + 2*tig + 1; }
                s = (cch[t][1][2] + ccl[t][1][2]) - h2; if (s > bestv[t*2+1]) { bestv[t*2+1] = s; bestk[t*2+1] = nb + 8 + 2*tig; }
                s = (cch[t][1][3] + ccl[t][1][3]) - h3; if (s > bestv[t*2+1]) { bestv[t*2+1] = s; bestk[t*2+1] = nb + 8 + 2*tig + 1; }
            }
        }
    }

    // ---- reduce across the 4 lanes sharing each row (tig dimension) ----
    #pragma unroll
    for (int i = 0; i < 4; ++i) {
        float v = bestv[i]; int k = bestk[i];
        #pragma unroll
        for (int off = 1; off <= 2; off <<= 1) {
            float ov = __shfl_xor_sync(0xffffffffu, v, off);
            int   ok = __shfl_xor_sync(0xffffffffu, k, off);
            if (ov > v || (ov == v && ok < k)) { v = ov; k = ok; }
        }
        if (tig == 0) bks[m0 + (i >> 1) * 16 + group + (i & 1) * 8] = k;
    }
    __syncthreads();

    // ---- write argmins (as float) ----
    out[RESULT_ELEMS + bg * 1024 + hw0 + tid] = (float)bks[tid];

    // ---- write result: out[bg*64+c][hw0+m] = w[c][k]*0.5 (coalesced over m) ----
    {
        int k = bks[tid];
        float* ob = out + (size_t)bg * 65536 + hw0 + tid;
        #pragma unroll 8
        for (int c = 0; c < 64; ++c)
            ob[(size_t)c * 1024] = w[c * 512 + k] * 0.5f;
    }
}

extern "C" void kernel_launch(void* const* d_in, const int* in_sizes, int n_in,
                              void* d_out, int out_size) {
    const float* x = (const float*)d_in[0];   // (64,256,32,32) fp32
    const float* w = (const float*)d_in[1];   // (64,512) fp32
    float* out = (float*)d_out;               // result ++ argmins

    cudaFuncSetAttribute(vq_mma, cudaFuncAttributeMaxDynamicSharedMemorySize, SMEM_SZ);

    prep_kernel<<<1, 512>>>(w);
    vq_mma<<<1024, 256, SMEM_SZ>>>(x, w, out);
}